// round 16
// baseline (speedup 1.0000x reference)
#include <cuda_runtime.h>
#include <cuda_bf16.h>

// PreprocessLayerTorch: MIC pairwise distances + shifts + element one-hot.
// Single fused kernel. Output layout (float32), flattened:
//   [0, n*4)                      onehot (n, 4)
//   [n*4, n*4 + n*n)              dist_masked (n, n)
//   [n*4 + n*n, +3nn)             shift (n, n, 3)
//
// FINAL (15-round search; DRAM-write-bound at ~6.4 TB/s, the sm_103a
// path-independent store ceiling):
//   Block = (1024 j's) x (4 i's), 256 threads, natural regalloc (47 regs,
//   5 CTAs/SM). j/i fractional coords computed in-block. Shift staged
//   warp-locally in smem so every global store is a warp-contiguous
//   streaming (.cs) STG.128. Magic-number round + rsqrt-based sqrt.

#define JPB  1024
#define TPB  256
#define ROWS 4

#define RND_MAGIC 12582912.0f   // 1.5 * 2^23

__device__ __forceinline__ float fast_rint(float x) {
    // round-to-nearest-even for |x| < 2^22
    return (x + RND_MAGIC) - RND_MAGIC;
}

__global__ __launch_bounds__(TPB)
void fused_kernel(const float* __restrict__ coord,
                  const float* __restrict__ cell,
                  const int* __restrict__ elems,
                  float* __restrict__ onehot_out,
                  float* __restrict__ dist_out,
                  float* __restrict__ shift_out, int n) {
    __shared__ float s_shift[TPB / 32][384];   // 12 KB, per-warp 128 j's * 3
    __shared__ float s_ifrac[ROWS][3];

    int t = threadIdx.x;
    int w = t >> 5;
    int l = t & 31;
    int base_j = blockIdx.x * JPB;
    int base_i = blockIdx.y * ROWS;
    int jw = base_j + w * 128;        // warp's j base
    int j0 = jw + l * 4;              // thread's first j
    bool act = (j0 < n);

    float c00 = __ldg(cell + 0), c01 = __ldg(cell + 1), c02 = __ldg(cell + 2);
    float c10 = __ldg(cell + 3), c11 = __ldg(cell + 4), c12 = __ldg(cell + 5);
    float c20 = __ldg(cell + 6), c21 = __ldg(cell + 7), c22 = __ldg(cell + 8);

    // h_inv (adjugate / det) — prologue-only registers.
    float det = c00 * (c11 * c22 - c12 * c21)
              - c01 * (c10 * c22 - c12 * c20)
              + c02 * (c10 * c21 - c11 * c20);
    float id = 1.0f / det;
    float i00 =  (c11 * c22 - c12 * c21) * id;
    float i01 = -(c01 * c22 - c02 * c21) * id;
    float i02 =  (c01 * c12 - c02 * c11) * id;
    float i10 = -(c10 * c22 - c12 * c20) * id;
    float i11 =  (c00 * c22 - c02 * c20) * id;
    float i12 = -(c00 * c12 - c02 * c10) * id;
    float i20 =  (c10 * c21 - c11 * c20) * id;
    float i21 = -(c00 * c21 - c01 * c20) * id;
    float i22 =  (c00 * c11 - c01 * c10) * id;

    // i-fracs -> smem (threads 0..ROWS-1)
    if (t < ROWS && base_i + t < n) {
        int i = base_i + t;
        float x = coord[3 * i + 0];
        float y = coord[3 * i + 1];
        float z = coord[3 * i + 2];
        float fx = x * i00 + y * i10 + z * i20;
        float fy = x * i01 + y * i11 + z * i21;
        float fz = x * i02 + y * i12 + z * i22;
        s_ifrac[t][0] = fx - floorf(fx);
        s_ifrac[t][1] = fy - floorf(fy);
        s_ifrac[t][2] = fz - floorf(fz);
    }

    // onehot: written once per i by the blockIdx.x == 0 column.
    if (blockIdx.x == 0 && t < ROWS && base_i + t < n) {
        int i = base_i + t;
        int e = elems[i];
        *reinterpret_cast<float4*>(onehot_out + 4 * i) =
            make_float4(e == 1 ? 1.0f : 0.0f, e == 6 ? 1.0f : 0.0f,
                        e == 7 ? 1.0f : 0.0f, e == 8 ? 1.0f : 0.0f);
    }

    // j-fracs for this thread's 4 atoms (3 aligned float4 loads).
    float fxs[4], fys[4], fzs[4];
    if (act) {
        const float4* cp = reinterpret_cast<const float4*>(coord + 3 * j0);
        float4 A = cp[0], B = cp[1], C = cp[2];
        float xs[4] = {A.x, A.w, B.z, C.y};
        float ys[4] = {A.y, B.x, B.w, C.z};
        float zs[4] = {A.z, B.y, C.x, C.w};
#pragma unroll
        for (int k = 0; k < 4; k++) {
            float fx = xs[k] * i00 + ys[k] * i10 + zs[k] * i20;
            float fy = xs[k] * i01 + ys[k] * i11 + zs[k] * i21;
            float fz = xs[k] * i02 + ys[k] * i12 + zs[k] * i22;
            fxs[k] = fx - floorf(fx);
            fys[k] = fy - floorf(fy);
            fzs[k] = fz - floorf(fz);
        }
    }
    __syncthreads();

    // Valid j count in this warp's region (n % 4 == 0 -> nq float4s exact).
    int jcount_w = n - jw;
    if (jcount_w > 128) jcount_w = 128;
    if (jcount_w < 0) jcount_w = 0;
    int nq = (jcount_w * 3) >> 2;     // valid shift float4s in warp region

    for (int r = 0; r < ROWS; r++) {
        int i = base_i + r;
        if (i >= n) break;

        float fxi = s_ifrac[r][0], fyi = s_ifrac[r][1], fzi = s_ifrac[r][2];

        if (act) {
            float dvals[4];
            float svals[12];
#pragma unroll
            for (int k = 0; k < 4; k++) {
                float dfx = fxs[k] - fxi;
                float dfy = fys[k] - fyi;
                float dfz = fzs[k] - fzi;

                // round-to-nearest-even via magic number (|dfrac| < 1)
                float rx = fast_rint(dfx);
                float ry = fast_rint(dfy);
                float rz = fast_rint(dfz);
                dfx -= rx;
                dfy -= ry;
                dfz -= rz;

                float dx = dfx * c00 + dfy * c10 + dfz * c20;
                float dy = dfx * c01 + dfy * c11 + dfz * c21;
                float dz = dfx * c02 + dfy * c12 + dfz * c22;

                float d2 = dx * dx + dy * dy + dz * dz;
                bool m = (d2 > 0.0f) && (d2 < 25.0f);  // RC = 5.0
                // sqrt(d2) = d2 * rsqrt(d2); 1 MUFU + 1 FMUL, ~1e-7 rel err
                dvals[k] = m ? d2 * __frsqrt_rn(d2) : 0.0f;
                svals[3 * k + 0] = -rx;
                svals[3 * k + 1] = -ry;
                svals[3 * k + 2] = -rz;
            }

            // dist: warp-contiguous streaming float4 store
            long long dbase = (long long)i * n + j0;
            __stcs(reinterpret_cast<float4*>(dist_out + dbase),
                   make_float4(dvals[0], dvals[1], dvals[2], dvals[3]));

            // stage shift (natural layout, 12 floats per lane)
            float* sm = &s_shift[w][l * 12];
            reinterpret_cast<float4*>(sm)[0] =
                make_float4(svals[0], svals[1], svals[2], svals[3]);
            reinterpret_cast<float4*>(sm)[1] =
                make_float4(svals[4], svals[5], svals[6], svals[7]);
            reinterpret_cast<float4*>(sm)[2] =
                make_float4(svals[8], svals[9], svals[10], svals[11]);
        }
        __syncwarp();

        // warp-local coalesced writeback: instruction s writes float4 (s*32+l)
        if (nq > 0) {
            long long sbase = ((long long)i * n + jw) * 3;
            const float4* smv = reinterpret_cast<const float4*>(&s_shift[w][0]);
            float4* dst = reinterpret_cast<float4*>(shift_out + sbase);
#pragma unroll
            for (int s = 0; s < 3; s++) {
                int q = s * 32 + l;
                if (q < nq) __stcs(dst + q, smv[q]);
            }
        }
        __syncwarp();   // protect smem before next row overwrites
    }
}

extern "C" void kernel_launch(void* const* d_in, const int* in_sizes, int n_in,
                              void* d_out, int out_size) {
    const float* coord = (const float*)d_in[0];   // (n, 3) float32
    const float* cell  = (const float*)d_in[1];   // (3, 3) float32
    const int*   elems = (const int*)d_in[2];     // (n,)   int32

    int n = in_sizes[0] / 3;

    float* out       = (float*)d_out;
    float* dist_out  = out + (long long)n * 4;      // n*n
    float* shift_out = dist_out + (long long)n * n; // n*n*3

    int jblocks = (n + JPB - 1) / JPB;
    int iblocks = (n + ROWS - 1) / ROWS;
    dim3 grid(jblocks, iblocks);
    fused_kernel<<<grid, TPB>>>(coord, cell, elems, out, dist_out, shift_out, n);
}